// round 1
// baseline (speedup 1.0000x reference)
#include <cuda_runtime.h>
#include <cstdint>

#define DIMX 4096      // model dim (= N_HEADS*HEAD_DIM)
#define BQ   8         // batch
#define KVD  1024      // N_KV_HEADS*HEAD_DIM

// Scratch (allocation-free rule: __device__ globals)
__device__ float g_x[BQ * KVD];    // up-projection result [8,1024]
__device__ float g_y[BQ * DIMX];   // final per-sequence row [8,4096]

__device__ __forceinline__ float warp_sum(float v) {
#pragma unroll
    for (int o = 16; o; o >>= 1) v += __shfl_xor_sync(0xffffffffu, v, o);
    return v;
}

// packed f32x2 FMA (Blackwell): acc(2xf32) += a(2xf32) * b(2xf32)
__device__ __forceinline__ void ffma2(unsigned long long& c,
                                      unsigned long long a,
                                      unsigned long long b) {
    asm("fma.rn.f32x2 %0, %1, %2, %0;" : "+l"(c) : "l"(a), "l"(b));
}

__device__ __forceinline__ float unpack_sum(unsigned long long p) {
    float2 f;
    f = *reinterpret_cast<float2*>(&p);
    return f.x + f.y;
}

// ---------------------------------------------------------------------------
// Kernel 1: x[8,1024] = E[8,4096] @ W_up[1024,4096]^T
// Grid: 256 blocks x 256 threads. Block handles 4 output rows j.
// ---------------------------------------------------------------------------
__global__ __launch_bounds__(256) void up_kernel(const float* __restrict__ E,
                                                 const float* __restrict__ Wup) {
    const int tid = threadIdx.x;
    const int j0 = blockIdx.x * 4;

    float acc[8][4];
#pragma unroll
    for (int b = 0; b < 8; b++)
#pragma unroll
        for (int r = 0; r < 4; r++) acc[b][r] = 0.0f;

#pragma unroll
    for (int c = 0; c < 4; c++) {
        const int kf = c * 1024 + tid * 4;  // float index, 16B aligned
        float4 e4[8];
#pragma unroll
        for (int b = 0; b < 8; b++)
            e4[b] = *reinterpret_cast<const float4*>(E + b * DIMX + kf);
        float4 w4[4];
#pragma unroll
        for (int r = 0; r < 4; r++)
            w4[r] = *reinterpret_cast<const float4*>(Wup + (size_t)(j0 + r) * DIMX + kf);
#pragma unroll
        for (int b = 0; b < 8; b++)
#pragma unroll
            for (int r = 0; r < 4; r++)
                acc[b][r] += e4[b].x * w4[r].x + e4[b].y * w4[r].y +
                             e4[b].z * w4[r].z + e4[b].w * w4[r].w;
    }

    __shared__ float red[8][32];
    const int lane = tid & 31, warp = tid >> 5;
#pragma unroll
    for (int b = 0; b < 8; b++)
#pragma unroll
        for (int r = 0; r < 4; r++) {
            float s = warp_sum(acc[b][r]);
            if (lane == 0) red[warp][b * 4 + r] = s;
        }
    __syncthreads();
    if (warp == 0) {
        float s = 0.0f;
#pragma unroll
        for (int w = 0; w < 8; w++) s += red[w][lane];
        const int b = lane >> 2, r = lane & 3;
        g_x[b * KVD + j0 + r] = s;
    }
}

// ---------------------------------------------------------------------------
// Kernel 2: y[8,4096] = expand(x)[8,4096] @ W_down[4096,4096]^T
// Grid: 128 blocks x 256 threads. Block caches expanded val in 128KB smem,
// each warp fully computes 4 output columns i (8 b's each), f32x2 FFMA.
// ---------------------------------------------------------------------------
extern __shared__ float s_val[];  // [8][4096]

__global__ __launch_bounds__(256, 1) void down_kernel(const float* __restrict__ Wdn) {
    const int tid = threadIdx.x;

    // Fill smem with kv-head-expanded val: val[b][h*128+d] = x[b][(h/4)*128+d]
    for (int idx = tid; idx < 8 * 4096; idx += 256) {
        const int b = idx >> 12;
        const int j = idx & 4095;
        const int h = j >> 7;
        const int jsrc = ((h >> 2) << 7) | (j & 127);
        s_val[idx] = g_x[b * KVD + jsrc];
    }
    __syncthreads();

    const int lane = tid & 31, warp = tid >> 5;
    const int i0 = blockIdx.x * 32 + warp * 4;

    unsigned long long acc[8][4];
#pragma unroll
    for (int b = 0; b < 8; b++)
#pragma unroll
        for (int r = 0; r < 4; r++) acc[b][r] = 0ull;

#pragma unroll 2
    for (int it = 0; it < 32; ++it) {
        const int jf = (it * 32 + lane) * 4;  // float index, 16B aligned
        ulonglong2 w[4];
#pragma unroll
        for (int r = 0; r < 4; r++)
            w[r] = *reinterpret_cast<const ulonglong2*>(Wdn + (size_t)(i0 + r) * DIMX + jf);
        ulonglong2 v[8];
#pragma unroll
        for (int b = 0; b < 8; b++)
            v[b] = *reinterpret_cast<const ulonglong2*>(s_val + b * 4096 + jf);
#pragma unroll
        for (int b = 0; b < 8; b++)
#pragma unroll
            for (int r = 0; r < 4; r++) {
                ffma2(acc[b][r], w[r].x, v[b].x);
                ffma2(acc[b][r], w[r].y, v[b].y);
            }
    }

#pragma unroll
    for (int b = 0; b < 8; b++)
#pragma unroll
        for (int r = 0; r < 4; r++) {
            float s = warp_sum(unpack_sum(acc[b][r]));
            if (lane == 0) g_y[b * DIMX + i0 + r] = s;
        }
}

// ---------------------------------------------------------------------------
// Kernel 3: broadcast y[b] to all token rows of sequence b (the 268MB write).
// Grid: ceil(nrows/32) blocks x 256 threads. Each thread holds a full
// 16-float slice of the current y-row in registers; reload only when the
// sequence id changes -> L2 read traffic ~0, pure streaming stores.
// ---------------------------------------------------------------------------
__global__ __launch_bounds__(256) void bcast_kernel(const int* __restrict__ seq,
                                                    float* __restrict__ out,
                                                    int nrows) {
    const int tid = threadIdx.x;

    // seqlen dtype defense: int32 expected; detect int64 (low words) fallback
    int s[8];
#pragma unroll
    for (int i = 0; i < 8; i++) s[i] = __ldg(seq + i);
    int tot = 0;
#pragma unroll
    for (int i = 0; i < 8; i++) tot += s[i];
    if (tot != nrows) {
#pragma unroll
        for (int i = 0; i < 8; i++) s[i] = __ldg(seq + 2 * i);
    }
    int pre[9];
    pre[0] = 0;
#pragma unroll
    for (int i = 0; i < 8; i++) pre[i + 1] = pre[i] + s[i];

    const int r0 = blockIdx.x * 32;
    int r1 = r0 + 32;
    if (r1 > nrows) r1 = nrows;

    int curb = -1;
    float4 v0, v1, v2, v3;

    for (int r = r0; r < r1; ++r) {
        int b = 0;
#pragma unroll
        for (int i = 0; i < 7; i++)
            if (r >= pre[b + 1]) ++b;
        if (b != curb) {
            const float4* yp = reinterpret_cast<const float4*>(g_y + b * DIMX);
            v0 = yp[tid];
            v1 = yp[tid + 256];
            v2 = yp[tid + 512];
            v3 = yp[tid + 768];
            curb = b;
        }
        float4* op = reinterpret_cast<float4*>(out + (size_t)r * DIMX);
        op[tid] = v0;
        op[tid + 256] = v1;
        op[tid + 512] = v2;
        op[tid + 768] = v3;
    }
}

// ---------------------------------------------------------------------------
extern "C" void kernel_launch(void* const* d_in, const int* in_sizes, int n_in,
                              void* d_out, int out_size) {
    const float* E   = (const float*)d_in[0];
    const float* Wup = (const float*)d_in[1];
    const float* Wdn = (const float*)d_in[2];
    const int*   seq = (const int*)d_in[3];
    float* out = (float*)d_out;

    const int nrows = out_size / DIMX;  // 16384

    up_kernel<<<256, 256>>>(E, Wup);

    cudaFuncSetAttribute(down_kernel, cudaFuncAttributeMaxDynamicSharedMemorySize,
                         8 * 4096 * (int)sizeof(float));
    down_kernel<<<128, 256, 8 * 4096 * sizeof(float)>>>(Wdn);

    const int nb = (nrows + 31) / 32;
    bcast_kernel<<<nb, 256>>>(seq, out, nrows);
}